// round 15
// baseline (speedup 1.0000x reference)
#include <cuda_runtime.h>
#include <cuda_fp16.h>
#include <math.h>
#include <stdint.h>

// ---------------- problem constants ----------------
#define BATCH   128
#define KDIM    49152      // 6144 * 8
#define NDIM    2048       // 256 * 8
#define KSPLIT  9          // 16 x 9 = 144 CTAs ~ one full wave on 148 SMs
#define KT      64         // K per A tile (tile granularity in g_xA)
#define BN      128        // N tile per CTA
#define NTILES  (KDIM / KT)   // 768 A tiles
#define NCHUNK  (NTILES / 2)  // 384 double-tile chunks (K=128 per chunk)
#define NQUAD   192           // 384/2 quads (4 tiles = 64KB of g_xA each)
#define LEAD    6             // chunks of conversion lead

// ---------------- scratch (device globals; no allocation allowed) ----------
__device__ __align__(16) __half g_xA[NTILES * 128 * 64];          // 12.6 MB
__device__ __align__(16) float g_part[KSPLIT * BATCH * NDIM];     // 9.4 MB
__device__ float g_W12[NDIM * 2];
__device__ float g_ob[2];
__device__ int   g_qflag[NQUAD];

// ================= PTX helpers ===============================================
__device__ __forceinline__ uint32_t smem_u32(const void* p) {
    uint32_t a;
    asm("{ .reg .u64 t; cvta.to.shared.u64 t, %1; cvt.u32.u64 %0, t; }" : "=r"(a) : "l"(p));
    return a;
}
__device__ __forceinline__ void cp_async16(uint32_t dst, const void* src) {
    asm volatile("cp.async.cg.shared.global [%0], [%1], 16;" :: "r"(dst), "l"(src) : "memory");
}
#define CP_COMMIT() asm volatile("cp.async.commit_group;" ::: "memory")
#define CP_WAIT0()  asm volatile("cp.async.wait_group 0;" ::: "memory")

// PDL (sm_90+ griddepcontrol — legal on compute_103)
#define GDC_WAIT()   asm volatile("griddepcontrol.wait;" ::: "memory")
#define GDC_LAUNCH() asm volatile("griddepcontrol.launch_dependents;")

__device__ __forceinline__ void ldsm4(uint32_t* r, uint32_t addr) {
    asm volatile("ldmatrix.sync.aligned.m8n8.x4.shared.b16 {%0,%1,%2,%3}, [%4];"
        : "=r"(r[0]), "=r"(r[1]), "=r"(r[2]), "=r"(r[3]) : "r"(addr));
}
__device__ __forceinline__ void ldsm4t(uint32_t* r, uint32_t addr) {
    asm volatile("ldmatrix.sync.aligned.m8n8.x4.trans.shared.b16 {%0,%1,%2,%3}, [%4];"
        : "=r"(r[0]), "=r"(r[1]), "=r"(r[2]), "=r"(r[3]) : "r"(addr));
}
__device__ __forceinline__ void mma_fp16(float* d, const uint32_t* a, const uint32_t* b) {
    asm volatile("mma.sync.aligned.m16n8k16.row.col.f32.f16.f16.f32 "
        "{%0,%1,%2,%3}, {%4,%5,%6,%7}, {%8,%9}, {%0,%1,%2,%3};"
        : "+f"(d[0]), "+f"(d[1]), "+f"(d[2]), "+f"(d[3])
        : "r"(a[0]), "r"(a[1]), "r"(a[2]), "r"(a[3]), "r"(b[0]), "r"(b[1]));
}
__device__ __forceinline__ uint32_t hfpair(float a, float b) {
    __half2 h = __floats2half2_rn(a, b);
    return *reinterpret_cast<uint32_t*>(&h);
}
__device__ __forceinline__ void wait_flag(const int* f) {
    int v;
    do {
        asm volatile("ld.acquire.gpu.global.b32 %0, [%1];" : "=r"(v) : "l"(f) : "memory");
    } while (v == 0);
}

// ---------------- in-GEMM A-tile conversion (quad = 4 tiles) ----------------
// Quad Q covers i in [32Q, 32Q+32), all 128 m. Bit-identical math to old convA.
__device__ void convert_quad(int Q, const float* __restrict__ x, int w, int lane) {
    const int i0 = 32 * Q + (lane & 7) * 4;
    char* dst = reinterpret_cast<char*>(g_xA);
#pragma unroll
    for (int g = 0; g < 4; g++) {
        int m = ((g * 8 + w) << 2) + (lane >> 3);
        const float* xp = x + (size_t)m * KDIM + i0;
        float4 v[8];
#pragma unroll
        for (int j = 0; j < 8; j++)
            v[j] = *reinterpret_cast<const float4*>(xp + j * 6144);
        const float* vf = reinterpret_cast<const float*>(v);
        uint32_t mask = ((uint32_t)m & 7) << 4;
#pragma unroll
        for (int e = 0; e < 4; e++) {
            int i = i0 + e;
            uint4 u = make_uint4(hfpair(vf[0 * 4 + e], vf[1 * 4 + e]),
                                 hfpair(vf[2 * 4 + e], vf[3 * 4 + e]),
                                 hfpair(vf[4 * 4 + e], vf[5 * 4 + e]),
                                 hfpair(vf[6 * 4 + e], vf[7 * 4 + e]));
            uint32_t off = (uint32_t)(i >> 3) * 16384 + (uint32_t)m * 128
                         + ((((uint32_t)i & 7) << 4) ^ mask);
            *reinterpret_cast<uint4*>(dst + off) = u;
        }
    }
    __threadfence();
    __syncthreads();
    if (w == 0 && lane == 0) {
        int* fp = g_qflag + Q;
        asm volatile("st.release.gpu.global.b32 [%0], %1;" :: "l"(fp), "r"(1) : "memory");
    }
}

// ---------------- kernel 1: pre (W12 collapse + flag zero) ------------------
__global__ void __launch_bounds__(256) k_pre(
    const float* __restrict__ li1_w, const float* __restrict__ li1_b,
    const float* __restrict__ li2_w, const float* __restrict__ li2_b)
{
    int bx = blockIdx.x;
    int t  = threadIdx.x;
    if (bx < 257) {
        __shared__ float s2[2000];
        for (int p = t; p < 2000; p += 256) s2[p] = li2_w[p];
        __syncthreads();
        int wq = t >> 5, l = t & 31;
        int j = bx * 8 + wq;            // 0..2056
        if (j <= NDIM) {
            const float* row = (j < NDIM) ? (li1_w + (size_t)j * 1000) : li1_b;
            float4 r[8];
#pragma unroll
            for (int it = 0; it < 7; it++)
                r[it] = *reinterpret_cast<const float4*>(row + (l + 32 * it) * 4);
            bool tail = (l < 26);
            if (tail)
                r[7] = *reinterpret_cast<const float4*>(row + (l + 224) * 4);

            float a0 = 0.f, a1 = 0.f, b0 = 0.f, b1 = 0.f;
#pragma unroll
            for (int it = 0; it < 7; it++) {
                int p0 = (l + 32 * it) * 4;
                a0 += r[it].x * s2[2 * p0 + 0] + r[it].z * s2[2 * p0 + 4];
                a1 += r[it].x * s2[2 * p0 + 1] + r[it].z * s2[2 * p0 + 5];
                b0 += r[it].y * s2[2 * p0 + 2] + r[it].w * s2[2 * p0 + 6];
                b1 += r[it].y * s2[2 * p0 + 3] + r[it].w * s2[2 * p0 + 7];
            }
            if (tail) {
                int p0 = (l + 224) * 4;
                a0 += r[7].x * s2[2 * p0 + 0] + r[7].z * s2[2 * p0 + 4];
                a1 += r[7].x * s2[2 * p0 + 1] + r[7].z * s2[2 * p0 + 5];
                b0 += r[7].y * s2[2 * p0 + 2] + r[7].w * s2[2 * p0 + 6];
                b1 += r[7].y * s2[2 * p0 + 3] + r[7].w * s2[2 * p0 + 7];
            }
            float v0 = a0 + b0, v1 = a1 + b1;
#pragma unroll
            for (int off = 16; off > 0; off >>= 1) {
                v0 += __shfl_down_sync(0xffffffffu, v0, off);
                v1 += __shfl_down_sync(0xffffffffu, v1, off);
            }
            if (l == 0) {
                if (j < NDIM) { g_W12[2 * j] = v0; g_W12[2 * j + 1] = v1; }
                else          { g_ob[0] = v0 + li2_b[0]; g_ob[1] = v1 + li2_b[1]; }
            }
        }
    } else {
        if (t < NQUAD) g_qflag[t] = 0;
    }
    GDC_LAUNCH();
}

// ---------------- kernel 2: fp16 split-K GEMM + in-shadow A conversion ------
#define BUF_BYTES  65536
#define SMEM_BYTES (2 * BUF_BYTES)

__global__ void __launch_bounds__(256, 1) k_gemm(const float* __restrict__ fc_w,
                                                 const float* __restrict__ x) {
    extern __shared__ __align__(1024) char smem[];
    const uint32_t sb = smem_u32(smem);
    const int t   = threadIdx.x;
    const int w   = t >> 5;
    const int l   = t & 31;
    const int wm  = w >> 2;
    const int wn  = w & 3;
    const int nbase = blockIdx.x * BN;
    const int s     = blockIdx.y;
    const int C0 = (s * NCHUNK) / KSPLIT;
    const int C1 = ((s + 1) * NCHUNK) / KSPLIT;

    // ---- owned quads (owner = split containing chunk 2Q+1, spread by x) ----
    const int Qlo = C0 >> 1, Qhi = C1 >> 1;     // exact partition of [0,192)
    const int Q0  = Qlo + (int)blockIdx.x;
    const int Q1  = Q0 + 16;
    const bool own0 = (Q0 < Qhi);
    const bool own1 = (Q1 < Qhi);
    const int t0 = own0 ? (2 * Q0 - C0 - LEAD) : 0x7fffffff;
    const int t1 = own1 ? (2 * Q1 - C0 - LEAD) : 0x7fffffff;

    uint32_t aoff[4], amask[4];
#pragma unroll
    for (int mt = 0; mt < 4; mt++) {
        int row = wm * 64 + mt * 16 + (l & 15);
        aoff[mt]  = (uint32_t)row * 128;
        amask[mt] = ((uint32_t)row & 7) << 4;
    }
    const uint32_t lcol = ((uint32_t)l >> 4) << 4;

    const uint32_t blane = (uint32_t)((l & 7) + ((l >> 3) & 1) * 8) * 256
                         + (((uint32_t)(64 * wn + 16 * (l >> 4))) ^ (((uint32_t)l & 7) << 4));
    const uint32_t bsts = (uint32_t)w * 256 + (((uint32_t)(8 * l)) ^ ((uint32_t)w << 4));

    float acc[64];
#pragma unroll
    for (int q = 0; q < 64; q++) acc[q] = 0.f;

    float4 bst[16];

    // ---- PRE-WAIT prologue: B(C0) from fc_w (independent of k_pre) ----
    {
        int kb = C0 * 128;
        const float* bp = fc_w + (size_t)(kb + w) * NDIM + nbase + 4 * l;
#pragma unroll
        for (int i = 0; i < 16; i++)
            bst[i] = *reinterpret_cast<const float4*>(bp + (size_t)(8 * i) * NDIM);
#pragma unroll
        for (int i = 0; i < 16; i++)
            *reinterpret_cast<uint2*>(smem + 32768 + bsts + i * 2048) =
                make_uint2(hfpair(bst[i].x, bst[i].y), hfpair(bst[i].z, bst[i].w));
    }

    // ---- wait for k_pre (flags zeroed), convert urgent owned quads ----
    GDC_WAIT();
    if (own0 && t0 <= 0) convert_quad(Q0, x, w, l);   // t1 = t0+32 > 0 always

    // ---- A(C0): wait its quad, then cp.async ----
    wait_flag(g_qflag + (C0 >> 1));
    {
        const char* srch = reinterpret_cast<const char*>(g_xA) + (size_t)C0 * 32768 + t * 16;
#pragma unroll
        for (int i = 0; i < 8; i++)
            cp_async16(sb + t * 16 + i * 4096, srch + i * 4096);
        CP_COMMIT();
    }

    // ---- main loop over this split's double-tile chunks ----
    for (int C = C0; C < C1; ++C) {
        const int cl = C - C0;
        const uint32_t cbuf = sb + (uint32_t)(cl & 1) * BUF_BYTES;
        const uint32_t nbuf = sb + (uint32_t)((cl + 1) & 1) * BUF_BYTES;

        // scheduled conversions (CTA-uniform conditions)
        if (own0 && cl == t0 && t0 > 0) convert_quad(Q0, x, w, l);
        if (own1 && cl == t1)           convert_quad(Q1, x, w, l);

        if (C + 1 < C1) {
            int kb = (C + 1) * 128;
            const float* bp = fc_w + (size_t)(kb + w) * NDIM + nbase + 4 * l;
#pragma unroll
            for (int i = 0; i < 16; i++)
                bst[i] = *reinterpret_cast<const float4*>(bp + (size_t)(8 * i) * NDIM);
        }

        CP_WAIT0();
        __syncthreads();

        if (C + 1 < C1) {
            wait_flag(g_qflag + ((C + 1) >> 1));
            const char* srch = reinterpret_cast<const char*>(g_xA) + (size_t)(C + 1) * 32768 + t * 16;
#pragma unroll
            for (int i = 0; i < 8; i++)
                cp_async16(nbuf + t * 16 + i * 4096, srch + i * 4096);
            CP_COMMIT();
        }

        const uint32_t Bh = cbuf + 32768;
#pragma unroll
        for (int ks = 0; ks < 8; ks++) {
            const uint32_t Ah = cbuf + ((ks & 4) ? 16384u : 0u);
            const uint32_t kcol = (uint32_t)((ks & 3) * 32) + lcol;
            uint32_t ah[4][4], bh[4][2];
#pragma unroll
            for (int mt = 0; mt < 4; mt++)
                ldsm4(ah[mt], Ah + aoff[mt] + (kcol ^ amask[mt]));
            {
                const uint32_t bb = Bh + (uint32_t)ks * 4096 + blane;
                uint32_t r[4];
                ldsm4t(r, bb);
                bh[0][0] = r[0]; bh[0][1] = r[1];
                bh[1][0] = r[2]; bh[1][1] = r[3];
                ldsm4t(r, bb ^ 32u);
                bh[2][0] = r[0]; bh[2][1] = r[1];
                bh[3][0] = r[2]; bh[3][1] = r[3];
            }
#pragma unroll
            for (int mt = 0; mt < 4; mt++)
#pragma unroll
                for (int nt = 0; nt < 4; nt++)
                    mma_fp16(acc + (mt * 4 + nt) * 4, ah[mt], bh[nt]);
        }

        if (C + 1 < C1) {
            char* bp = smem + (nbuf - sb);
#pragma unroll
            for (int i = 0; i < 16; i++)
                *reinterpret_cast<uint2*>(bp + 32768 + bsts + i * 2048) =
                    make_uint2(hfpair(bst[i].x, bst[i].y), hfpair(bst[i].z, bst[i].w));
        }
    }

    // ---- epilogue: write partials, then trigger fuse ----
    float* op = g_part + (size_t)s * BATCH * NDIM;
#pragma unroll
    for (int mt = 0; mt < 4; mt++) {
        int m = wm * 64 + mt * 16 + (l >> 2);
#pragma unroll
        for (int nt = 0; nt < 4; nt++) {
            int n = nbase + wn * 32 + nt * 8 + (l & 3) * 2;
            const float* d = acc + (mt * 4 + nt) * 4;
            *reinterpret_cast<float2*>(op + (size_t)m * NDIM + n)       = make_float2(d[0], d[1]);
            *reinterpret_cast<float2*>(op + (size_t)(m + 8) * NDIM + n) = make_float2(d[2], d[3]);
        }
    }
    GDC_LAUNCH();
}

// ---------------- kernel 3: fused per-batch pipeline, 512 thr, PDL ----------
__global__ void __launch_bounds__(512) k_fuse(
    const float* __restrict__ fc_b,
    const float* __restrict__ ln1_s, const float* __restrict__ ln1_b,
    const float* __restrict__ ln2_s, const float* __restrict__ ln2_b,
    const float* __restrict__ Wq, const float* __restrict__ Wk, const float* __restrict__ Wv,
    const float* __restrict__ Wg, const float* __restrict__ Wo,
    const float* __restrict__ gn_w, const float* __restrict__ gn_b,
    const float* __restrict__ w1, const float* __restrict__ b1,
    const float* __restrict__ w2, const float* __restrict__ b2,
    float* __restrict__ out)
{
    int b   = blockIdx.x;
    int tid = threadIdx.x;
    int l   = tid & 255;
    int hg  = tid >> 8;

    __shared__ float4 sK4[2][256];
    __shared__ float4 sV4[2][256][2];
    __shared__ float  sGP[2][256];
    __shared__ float  syc[256][17];
    __shared__ float  sRed[8][2];
    __shared__ float  swq[64], swk[64], swv[128], swg[128], swo[128];
    __shared__ float  sgnw[16], sgnb[16], sw1[64], sw2[64];
    __shared__ float  sb1[8], sb2[8], sl1s[8], sl1b[8], sl2s[8], sl2b[8];

    if (tid < 64)  { swq[tid] = Wq[tid]; swk[tid] = Wk[tid]; sw1[tid] = w1[tid]; sw2[tid] = w2[tid]; }
    else if (tid < 192) { int u = tid - 64; swv[u] = Wv[u]; swg[u] = Wg[u]; swo[u] = Wo[u]; }
    else if (tid < 208) { int u = tid - 192; sgnw[u] = gn_w[u]; sgnb[u] = gn_b[u]; }
    else if (tid < 216) { int u = tid - 208; sb1[u] = b1[u]; sb2[u] = b2[u];
                          sl1s[u] = ln1_s[u]; sl1b[u] = ln1_b[u];
                          sl2s[u] = ln2_s[u]; sl2b[u] = ln2_b[u]; }

    float fl = (float)l;
    float c0 = cosf(fl), s0 = sinf(fl);
    float c1 = cosf(fl * 0.01f), s1 = sinf(fl * 0.01f);
    float e0 = exp2f(fl * (-1.807354922f / 512.0f));
    float e1 = exp2f(fl * (-0.637429921f / 512.0f));
    float ie0 = 1.0f / e0, ie1 = 1.0f / e1;
    const float l2g[2] = { -0.04580368961f, -0.00281970977f };

    float4 hb0 = *reinterpret_cast<const float4*>(fc_b + l * 8);
    float4 hb1 = *reinterpret_cast<const float4*>(fc_b + l * 8 + 4);

    GDC_WAIT();

    float X[8];
    {
        X[0] = hb0.x; X[1] = hb0.y; X[2] = hb0.z; X[3] = hb0.w;
        X[4] = hb1.x; X[5] = hb1.y; X[6] = hb1.z; X[7] = hb1.w;
#pragma unroll
        for (int s = 0; s < KSPLIT; s++) {
            const float* pp = g_part + (size_t)s * (BATCH * NDIM) + b * NDIM + l * 8;
            float4 p0 = *reinterpret_cast<const float4*>(pp);
            float4 p1 = *reinterpret_cast<const float4*>(pp + 4);
            X[0] += p0.x; X[1] += p0.y; X[2] += p0.z; X[3] += p0.w;
            X[4] += p1.x; X[5] += p1.y; X[6] += p1.z; X[7] += p1.w;
        }
    }
    __syncthreads();

    float Xn[8];
    {
        float mu = 0.f;
#pragma unroll
        for (int d = 0; d < 8; d++) mu += X[d];
        mu *= 0.125f;
        float var = 0.f;
#pragma unroll
        for (int d = 0; d < 8; d++) { float tt = X[d] - mu; var += tt * tt; }
        var *= 0.125f;
        float inv = rsqrtf(var + 1e-5f);
#pragma unroll
        for (int d = 0; d < 8; d++) Xn[d] = (X[d] - mu) * inv * sl1s[d] + sl1b[d];
    }

    {
        const float* wq = swq + hg * 32;
        const float* wk = swk + hg * 32;
        const float* wv = swv + hg * 64;

        float q0 = 0, q1 = 0, q2 = 0, q3 = 0, k0 = 0, k1 = 0, k2 = 0, k3 = 0;
#pragma unroll
        for (int d = 0; d < 8; d++) {
            float xv = Xn[d];
            q0 += xv * wq[d * 4 + 0]; q1 += xv * wq[d * 4 + 1];
            q2 += xv * wq[d * 4 + 2]; q3 += xv * wq[d * 4 + 3];
            k0 += xv * wk[d * 4 + 0]; k1 += xv * wk[d * 4 + 1];
            k2 += xv * wk[d * 4 + 2]; k3 += xv * wk[d * 4 + 3];
        }
        float Q0 = (q0 * c0 - q1 * s0) * e0;
        float Q1 = (q1 * c0 + q0 * s0) * e0;
        float Q2 = (q2 * c1 - q3 * s1) * e1;
        float Q3 = (q3 * c1 + q2 * s1) * e1;
        float K0 = (k0 * c0 - k1 * s0) * ie0;
        float K1 = (k1 * c0 + k0 * s0) * ie0;
        float K2 = (k2 * c1 - k3 * s1) * ie1;
        float K3 = (k3 * c1 + k2 * s1) * ie1;

        float V[8];
#pragma unroll
        for (int f = 0; f < 8; f++) {
            float a = 0.f;
#pragma unroll
            for (int d = 0; d < 8; d++) a += Xn[d] * wv[d * 8 + f];
            V[f] = a;
        }

        sK4[hg][l] = make_float4(K0, K1, K2, K3);
        sV4[hg][l][0] = make_float4(V[0], V[1], V[2], V[3]);
        sV4[hg][l][1] = make_float4(V[4], V[5], V[6], V[7]);
        sGP[hg][l] = exp2f(-fl * l2g[hg]);
        float gpn = exp2f(fl * l2g[hg]);
        __syncthreads();

        float a0 = 0, a1 = 0, a2 = 0, a3 = 0, a4 = 0, a5 = 0, a6 = 0, a7 = 0;
        const float4* kp = sK4[hg];
        const float4 (*vp)[2] = sV4[hg];
        const float* gp = sGP[hg];
        for (int m = 0; m <= l; ++m) {
            float4 kv = kp[m];
            float wgt = (Q0 * kv.x + Q1 * kv.y + Q2 * kv.z + Q3 * kv.w) * gpn * gp[m];
            float4 v0 = vp[m][0], v1 = vp[m][1];
            a0 += wgt * v0.x; a1 += wgt * v0.y; a2 += wgt * v0.z; a3 += wgt * v0.w;
            a4 += wgt * v1.x; a5 += wgt * v1.y; a6 += wgt * v1.z; a7 += wgt * v1.w;
        }
        float* yr = syc[l] + hg * 8;
        yr[0] = a0; yr[1] = a1; yr[2] = a2; yr[3] = a3;
        yr[4] = a4; yr[5] = a5; yr[6] = a6; yr[7] = a7;
    }
    __syncthreads();

    if (hg == 0) {
        float yc[16];
#pragma unroll
        for (int j = 0; j < 16; j++) yc[j] = syc[l][j];

        float gn[16];
#pragma unroll
        for (int g = 0; g < 2; g++) {
            float mu = 0.f;
#pragma unroll
            for (int jj = 0; jj < 8; jj++) mu += yc[g * 8 + jj];
            mu *= 0.125f;
            float var = 0.f;
#pragma unroll
            for (int jj = 0; jj < 8; jj++) { float tt = yc[g * 8 + jj] - mu; var += tt * tt; }
            var *= 0.125f;
            float inv = rsqrtf(var + 1e-5f);
#pragma unroll
            for (int jj = 0; jj < 8; jj++)
                gn[g * 8 + jj] = (yc[g * 8 + jj] - mu) * inv * sgnw[g * 8 + jj] + sgnb[g * 8 + jj];
        }

        float msr[8] = {0, 0, 0, 0, 0, 0, 0, 0};
#pragma unroll
        for (int j = 0; j < 16; j++) {
            float gt = 0.f;
#pragma unroll
            for (int d = 0; d < 8; d++) gt += Xn[d] * swg[d * 16 + j];
            gt = gt / (1.0f + expf(-gt));
            float val = gt * gn[j];
#pragma unroll
            for (int d = 0; d < 8; d++) msr[d] += val * swo[j * 8 + d];
        }

        float Y[8], Z[8];
#pragma unroll
        for (int d = 0; d < 8; d++) Y[d] = msr[d] + X[d];
        {
            float mu = 0.f;
#pragma unroll
            for (int d = 0; d < 8; d++) mu += Y[d];
            mu *= 0.125f;
            float var = 0.f;
#pragma unroll
            for (int d = 0; d < 8; d++) { float tt = Y[d] - mu; var += tt * tt; }
            var *= 0.125f;
            float inv = rsqrtf(var + 1e-5f);
#pragma unroll
            for (int d = 0; d < 8; d++) Z[d] = (Y[d] - mu) * inv * sl2s[d] + sl2b[d];
        }

        float f1[8];
#pragma unroll
        for (int e = 0; e < 8; e++) {
            float a = sb1[e];
#pragma unroll
            for (int d = 0; d < 8; d++) a += Z[d] * sw1[d * 8 + e];
            f1[e] = 0.5f * a * (1.0f + erff(a * 0.70710678118654752f));
        }

        float p0 = 0.f, p1 = 0.f;
#pragma unroll
        for (int d = 0; d < 8; d++) {
            float a = sb2[d];
#pragma unroll
            for (int e = 0; e < 8; e++) a += f1[e] * sw2[e * 8 + d];
            float xf = a + Y[d];
            p0 += xf * g_W12[(l * 8 + d) * 2];
            p1 += xf * g_W12[(l * 8 + d) * 2 + 1];
        }

#pragma unroll
        for (int off = 16; off > 0; off >>= 1) {
            p0 += __shfl_down_sync(0xffffffffu, p0, off);
            p1 += __shfl_down_sync(0xffffffffu, p1, off);
        }
        if ((l & 31) == 0) { sRed[l >> 5][0] = p0; sRed[l >> 5][1] = p1; }
    }
    __syncthreads();
    if (tid == 0) {
        float o0 = g_ob[0], o1 = g_ob[1];
#pragma unroll
        for (int ww = 0; ww < 8; ww++) { o0 += sRed[ww][0]; o1 += sRed[ww][1]; }
        out[b * 2 + 0] = o0;
        out[b * 2 + 1] = o1;
    }
}

// ---------------- launch (PDL chain: pre -> gemm -> fuse) --------------------
extern "C" void kernel_launch(void* const* d_in, const int* in_sizes, int n_in,
                              void* d_out, int out_size) {
    const float* x      = (const float*)d_in[0];
    const float* fc_w   = (const float*)d_in[1];
    const float* fc_b   = (const float*)d_in[2];
    const float* ln1_s  = (const float*)d_in[3];
    const float* ln1_b  = (const float*)d_in[4];
    const float* ln2_s  = (const float*)d_in[5];
    const float* ln2_b  = (const float*)d_in[6];
    const float* Wq     = (const float*)d_in[7];
    const float* Wk     = (const float*)d_in[8];
    const float* Wv     = (const float*)d_in[9];
    const float* Wg     = (const float*)d_in[10];
    const float* Wo     = (const float*)d_in[11];
    const float* gn_w   = (const float*)d_in[12];
    const float* gn_b   = (const float*)d_in[13];
    const float* ffn_w1 = (const float*)d_in[14];
    const float* ffn_b1 = (const float*)d_in[15];
    const float* ffn_w2 = (const float*)d_in[16];
    const float* ffn_b2 = (const float*)d_in[17];
    const float* li1_w  = (const float*)d_in[18];
    const float* li1_b  = (const float*)d_in[19];
    const float* li2_w  = (const float*)d_in[20];
    const float* li2_b  = (const float*)d_in[21];

    cudaFuncSetAttribute(k_gemm, cudaFuncAttributeMaxDynamicSharedMemorySize, SMEM_BYTES);

    // pre: W12 + flag zeroing (normal launch)
    k_pre<<<258, 256>>>(li1_w, li1_b, li2_w, li2_b);

    // gemm: PDL (B prologue overlaps k_pre; flags/conversions after wait)
    {
        cudaLaunchAttribute attr[1];
        attr[0].id = cudaLaunchAttributeProgrammaticStreamSerialization;
        attr[0].val.programmaticStreamSerializationAllowed = 1;
        cudaLaunchConfig_t cfg = {};
        cfg.gridDim = dim3(NDIM / BN, KSPLIT, 1);
        cfg.blockDim = dim3(256, 1, 1);
        cfg.dynamicSmemBytes = SMEM_BYTES;
        cfg.stream = 0;
        cfg.attrs = attr;
        cfg.numAttrs = 1;
        cudaLaunchKernelEx(&cfg, k_gemm, fc_w, x);
    }

    // fuse: PDL
    {
        cudaLaunchAttribute attr[1];
        attr[0].id = cudaLaunchAttributeProgrammaticStreamSerialization;
        attr[0].val.programmaticStreamSerializationAllowed = 1;
        cudaLaunchConfig_t cfg = {};
        cfg.gridDim = dim3(BATCH, 1, 1);
        cfg.blockDim = dim3(512, 1, 1);
        cfg.dynamicSmemBytes = 0;
        cfg.stream = 0;
        cfg.attrs = attr;
        cfg.numAttrs = 1;
        cudaLaunchKernelEx(&cfg, k_fuse, fc_b, ln1_s, ln1_b, ln2_s, ln2_b,
                           Wq, Wk, Wv, Wg, Wo, gn_w, gn_b,
                           ffn_w1, ffn_b1, ffn_w2, ffn_b2,
                           (float*)d_out);
    }
}

// round 16
// speedup vs baseline: 1.2543x; 1.2543x over previous
#include <cuda_runtime.h>
#include <cuda_fp16.h>
#include <math.h>
#include <stdint.h>

// ---------------- problem constants ----------------
#define BATCH   128
#define KDIM    49152      // 6144 * 8
#define NDIM    2048       // 256 * 8
#define KSPLIT  9          // 16 x 9 = 144 CTAs ~ one full wave on 148 SMs
#define KT      64         // K per A tile (tile granularity in g_xA)
#define BN      128        // N tile per CTA
#define NTILES  (KDIM / KT)   // 768 A tiles
#define NCHUNK  (NTILES / 2)  // 384 double-tile chunks (K=128 per chunk)

// ---------------- scratch (device globals; no allocation allowed) ----------
__device__ __align__(16) __half g_xA[NTILES * 128 * 64];          // 12.6 MB
__device__ __align__(16) float g_part[KSPLIT * BATCH * NDIM];     // 9.4 MB
__device__ float g_W12[NDIM * 2];
__device__ float g_ob[2];

// ================= PTX helpers ===============================================
__device__ __forceinline__ uint32_t smem_u32(const void* p) {
    uint32_t a;
    asm("{ .reg .u64 t; cvta.to.shared.u64 t, %1; cvt.u32.u64 %0, t; }" : "=r"(a) : "l"(p));
    return a;
}
__device__ __forceinline__ void cp_async16(uint32_t dst, const void* src) {
    asm volatile("cp.async.cg.shared.global [%0], [%1], 16;" :: "r"(dst), "l"(src) : "memory");
}
#define CP_COMMIT() asm volatile("cp.async.commit_group;" ::: "memory")
#define CP_WAIT0()  asm volatile("cp.async.wait_group 0;" ::: "memory")

// PDL (sm_90+ griddepcontrol — legal on compute_103)
#define GDC_WAIT()   asm volatile("griddepcontrol.wait;" ::: "memory")
#define GDC_LAUNCH() asm volatile("griddepcontrol.launch_dependents;")

__device__ __forceinline__ void ldsm4(uint32_t* r, uint32_t addr) {
    asm volatile("ldmatrix.sync.aligned.m8n8.x4.shared.b16 {%0,%1,%2,%3}, [%4];"
        : "=r"(r[0]), "=r"(r[1]), "=r"(r[2]), "=r"(r[3]) : "r"(addr));
}
__device__ __forceinline__ void ldsm4t(uint32_t* r, uint32_t addr) {
    asm volatile("ldmatrix.sync.aligned.m8n8.x4.trans.shared.b16 {%0,%1,%2,%3}, [%4];"
        : "=r"(r[0]), "=r"(r[1]), "=r"(r[2]), "=r"(r[3]) : "r"(addr));
}
__device__ __forceinline__ void mma_fp16(float* d, const uint32_t* a, const uint32_t* b) {
    asm volatile("mma.sync.aligned.m16n8k16.row.col.f32.f16.f16.f32 "
        "{%0,%1,%2,%3}, {%4,%5,%6,%7}, {%8,%9}, {%0,%1,%2,%3};"
        : "+f"(d[0]), "+f"(d[1]), "+f"(d[2]), "+f"(d[3])
        : "r"(a[0]), "r"(a[1]), "r"(a[2]), "r"(a[3]), "r"(b[0]), "r"(b[1]));
}
__device__ __forceinline__ uint32_t hfpair(float a, float b) {
    __half2 h = __floats2half2_rn(a, b);
    return *reinterpret_cast<uint32_t*>(&h);
}

// ---------------- kernel 1: merged prep (convA MLP=16 + block-per-row W12) --
// blocks [0, 384): convA (unchanged from best kernel)
// blocks [384, 384+2049): W12 row j = bx-384; thread t covers p=4t..4t+3.
__global__ void __launch_bounds__(256) k_prep(
    const float* __restrict__ x,
    const float* __restrict__ li1_w, const float* __restrict__ li1_b,
    const float* __restrict__ li2_w, const float* __restrict__ li2_b)
{
    int bx = blockIdx.x;
    if (bx < 384) {
        int m  = bx & 127;
        int yb = bx >> 7;                       // 0..2
        const float* xp = x + (size_t)m * KDIM;
        char* dst = reinterpret_cast<char*>(g_xA);
        uint32_t mask = ((uint32_t)m & 7) << 4;

        int i0a = (yb * 256 + threadIdx.x) * 4;
        int i0b = i0a + 3072;
        float4 va[8], vb[8];
#pragma unroll
        for (int j = 0; j < 8; j++)
            va[j] = *reinterpret_cast<const float4*>(xp + j * 6144 + i0a);
#pragma unroll
        for (int j = 0; j < 8; j++)
            vb[j] = *reinterpret_cast<const float4*>(xp + j * 6144 + i0b);

#pragma unroll
        for (int g = 0; g < 2; g++) {
            const float* vf = reinterpret_cast<const float*>(g == 0 ? va : vb);
            int i0 = g == 0 ? i0a : i0b;
            uint32_t base = (uint32_t)(i0 >> 3) * 16384 + (uint32_t)m * 128;
#pragma unroll
            for (int e = 0; e < 4; e++) {
                int i = i0 + e;
                uint32_t h0 = hfpair(vf[0 * 4 + e], vf[1 * 4 + e]);
                uint32_t h1 = hfpair(vf[2 * 4 + e], vf[3 * 4 + e]);
                uint32_t h2 = hfpair(vf[4 * 4 + e], vf[5 * 4 + e]);
                uint32_t h3 = hfpair(vf[6 * 4 + e], vf[7 * 4 + e]);
                uint32_t off = base + ((((uint32_t)i & 7) << 4) ^ mask);
                *reinterpret_cast<uint4*>(dst + off) = make_uint4(h0, h1, h2, h3);
            }
        }
    } else {
        int j = bx - 384;                 // 0..2048
        int t = threadIdx.x;
        const float* row = (j < NDIM) ? (li1_w + (size_t)j * 1000) : li1_b;
        float v0 = 0.f, v1 = 0.f;
        if (t < 250) {
            float4 r  = *reinterpret_cast<const float4*>(row + t * 4);
            float4 s0 = *reinterpret_cast<const float4*>(li2_w + t * 8);
            float4 s1 = *reinterpret_cast<const float4*>(li2_w + t * 8 + 4);
            v0 = r.x * s0.x + r.y * s0.z + r.z * s1.x + r.w * s1.z;
            v1 = r.x * s0.y + r.y * s0.w + r.z * s1.y + r.w * s1.w;
        }
#pragma unroll
        for (int off = 16; off > 0; off >>= 1) {
            v0 += __shfl_down_sync(0xffffffffu, v0, off);
            v1 += __shfl_down_sync(0xffffffffu, v1, off);
        }
        __shared__ float red[8][2];
        int wq = t >> 5, l = t & 31;
        if (l == 0) { red[wq][0] = v0; red[wq][1] = v1; }
        __syncthreads();
        if (t == 0) {
            float a0 = 0.f, a1 = 0.f;
#pragma unroll
            for (int ww = 0; ww < 8; ww++) { a0 += red[ww][0]; a1 += red[ww][1]; }
            if (j < NDIM) { g_W12[2 * j] = a0; g_W12[2 * j + 1] = a1; }
            else          { g_ob[0] = a0 + li2_b[0]; g_ob[1] = a1 + li2_b[1]; }
        }
    }
    GDC_LAUNCH();   // writes done -> let k_gemm's post-wait section proceed
}

// ---------------- kernel 2: fp16 split-K GEMM, K=128 per stage, PDL ---------
#define BUF_BYTES  65536
#define SMEM_BYTES (2 * BUF_BYTES)

__global__ void __launch_bounds__(256, 1) k_gemm(const float* __restrict__ fc_w) {
    extern __shared__ __align__(1024) char smem[];
    const uint32_t sb = smem_u32(smem);
    const int t   = threadIdx.x;
    const int w   = t >> 5;
    const int l   = t & 31;
    const int wm  = w >> 2;
    const int wn  = w & 3;
    const int nbase = blockIdx.x * BN;
    const int s     = blockIdx.y;
    const int C0 = (s * NCHUNK) / KSPLIT;
    const int C1 = ((s + 1) * NCHUNK) / KSPLIT;

    uint32_t aoff[4], amask[4];
#pragma unroll
    for (int mt = 0; mt < 4; mt++) {
        int row = wm * 64 + mt * 16 + (l & 15);
        aoff[mt]  = (uint32_t)row * 128;
        amask[mt] = ((uint32_t)row & 7) << 4;
    }
    const uint32_t lcol = ((uint32_t)l >> 4) << 4;

    const uint32_t blane = (uint32_t)((l & 7) + ((l >> 3) & 1) * 8) * 256
                         + (((uint32_t)(64 * wn + 16 * (l >> 4))) ^ (((uint32_t)l & 7) << 4));
    const uint32_t bsts = (uint32_t)w * 256 + (((uint32_t)(8 * l)) ^ ((uint32_t)w << 4));

    float acc[64];
#pragma unroll
    for (int q = 0; q < 64; q++) acc[q] = 0.f;

    float4 bst[16];

    // ---- PRE-WAIT prologue: B(C0) from fc_w (independent of prep) ----
    {
        int kb = C0 * 128;
        const float* bp = fc_w + (size_t)(kb + w) * NDIM + nbase + 4 * l;
#pragma unroll
        for (int i = 0; i < 16; i++)
            bst[i] = *reinterpret_cast<const float4*>(bp + (size_t)(8 * i) * NDIM);
#pragma unroll
        for (int i = 0; i < 16; i++)
            *reinterpret_cast<uint2*>(smem + 32768 + bsts + i * 2048) =
                make_uint2(hfpair(bst[i].x, bst[i].y), hfpair(bst[i].z, bst[i].w));
    }

    // ---- wait for prep (g_xA ready), then A(C0) cp.async ----
    GDC_WAIT();
    {
        const char* srch = reinterpret_cast<const char*>(g_xA) + (size_t)C0 * 32768 + t * 16;
#pragma unroll
        for (int i = 0; i < 8; i++)
            cp_async16(sb + t * 16 + i * 4096, srch + i * 4096);
        CP_COMMIT();
    }

    // ---- main loop over this split's double-tile chunks ----
    for (int C = C0; C < C1; ++C) {
        const int cl = C - C0;
        const uint32_t cbuf = sb + (uint32_t)(cl & 1) * BUF_BYTES;
        const uint32_t nbuf = sb + (uint32_t)((cl + 1) & 1) * BUF_BYTES;

        if (C + 1 < C1) {
            int kb = (C + 1) * 128;
            const float* bp = fc_w + (size_t)(kb + w) * NDIM + nbase + 4 * l;
#pragma unroll
            for (int i = 0; i < 16; i++)
                bst[i] = *reinterpret_cast<const float4*>(bp + (size_t)(8 * i) * NDIM);
        }

        CP_WAIT0();
        __syncthreads();

        if (C + 1 < C1) {
            const char* srch = reinterpret_cast<const char*>(g_xA) + (size_t)(C + 1) * 32768 + t * 16;
#pragma unroll
            for (int i = 0; i < 8; i++)
                cp_async16(nbuf + t * 16 + i * 4096, srch + i * 4096);
            CP_COMMIT();
        }

        const uint32_t Bh = cbuf + 32768;
#pragma unroll
        for (int ks = 0; ks < 8; ks++) {
            const uint32_t Ah = cbuf + ((ks & 4) ? 16384u : 0u);
            const uint32_t kcol = (uint32_t)((ks & 3) * 32) + lcol;
            uint32_t ah[4][4], bh[4][2];
#pragma unroll
            for (int mt = 0; mt < 4; mt++)
                ldsm4(ah[mt], Ah + aoff[mt] + (kcol ^ amask[mt]));
            {
                const uint32_t bb = Bh + (uint32_t)ks * 4096 + blane;
                uint32_t r[4];
                ldsm4t(r, bb);
                bh[0][0] = r[0]; bh[0][1] = r[1];
                bh[1][0] = r[2]; bh[1][1] = r[3];
                ldsm4t(r, bb ^ 32u);
                bh[2][0] = r[0]; bh[2][1] = r[1];
                bh[3][0] = r[2]; bh[3][1] = r[3];
            }
#pragma unroll
            for (int mt = 0; mt < 4; mt++)
#pragma unroll
                for (int nt = 0; nt < 4; nt++)
                    mma_fp16(acc + (mt * 4 + nt) * 4, ah[mt], bh[nt]);
        }

        if (C + 1 < C1) {
            char* bp = smem + (nbuf - sb);
#pragma unroll
            for (int i = 0; i < 16; i++)
                *reinterpret_cast<uint2*>(bp + 32768 + bsts + i * 2048) =
                    make_uint2(hfpair(bst[i].x, bst[i].y), hfpair(bst[i].z, bst[i].w));
        }
    }

    // ---- epilogue: write partials, then trigger fuse ----
    float* op = g_part + (size_t)s * BATCH * NDIM;
#pragma unroll
    for (int mt = 0; mt < 4; mt++) {
        int m = wm * 64 + mt * 16 + (l >> 2);
#pragma unroll
        for (int nt = 0; nt < 4; nt++) {
            int n = nbase + wn * 32 + nt * 8 + (l & 3) * 2;
            const float* d = acc + (mt * 4 + nt) * 4;
            *reinterpret_cast<float2*>(op + (size_t)m * NDIM + n)       = make_float2(d[0], d[1]);
            *reinterpret_cast<float2*>(op + (size_t)(m + 8) * NDIM + n) = make_float2(d[2], d[3]);
        }
    }
    GDC_LAUNCH();
}

// ---------------- kernel 3: fused per-batch pipeline, 512 thr, PDL ----------
__global__ void __launch_bounds__(512) k_fuse(
    const float* __restrict__ fc_b,
    const float* __restrict__ ln1_s, const float* __restrict__ ln1_b,
    const float* __restrict__ ln2_s, const float* __restrict__ ln2_b,
    const float* __restrict__ Wq, const float* __restrict__ Wk, const float* __restrict__ Wv,
    const float* __restrict__ Wg, const float* __restrict__ Wo,
    const float* __restrict__ gn_w, const float* __restrict__ gn_b,
    const float* __restrict__ w1, const float* __restrict__ b1,
    const float* __restrict__ w2, const float* __restrict__ b2,
    float* __restrict__ out)
{
    int b   = blockIdx.x;
    int tid = threadIdx.x;
    int l   = tid & 255;
    int hg  = tid >> 8;

    __shared__ float4 sK4[2][256];
    __shared__ float4 sV4[2][256][2];
    __shared__ float  sGP[2][256];
    __shared__ float  syc[256][17];
    __shared__ float  sRed[8][2];
    __shared__ float  swq[64], swk[64], swv[128], swg[128], swo[128];
    __shared__ float  sgnw[16], sgnb[16], sw1[64], sw2[64];
    __shared__ float  sb1[8], sb2[8], sl1s[8], sl1b[8], sl2s[8], sl2b[8];

    // ---- PRE-WAIT: weights (harness inputs) + per-position constants ----
    if (tid < 64)  { swq[tid] = Wq[tid]; swk[tid] = Wk[tid]; sw1[tid] = w1[tid]; sw2[tid] = w2[tid]; }
    else if (tid < 192) { int u = tid - 64; swv[u] = Wv[u]; swg[u] = Wg[u]; swo[u] = Wo[u]; }
    else if (tid < 208) { int u = tid - 192; sgnw[u] = gn_w[u]; sgnb[u] = gn_b[u]; }
    else if (tid < 216) { int u = tid - 208; sb1[u] = b1[u]; sb2[u] = b2[u];
                          sl1s[u] = ln1_s[u]; sl1b[u] = ln1_b[u];
                          sl2s[u] = ln2_s[u]; sl2b[u] = ln2_b[u]; }

    float fl = (float)l;
    float c0 = cosf(fl), s0 = sinf(fl);
    float c1 = cosf(fl * 0.01f), s1 = sinf(fl * 0.01f);
    float e0 = exp2f(fl * (-1.807354922f / 512.0f));
    float e1 = exp2f(fl * (-0.637429921f / 512.0f));
    float ie0 = 1.0f / e0, ie1 = 1.0f / e1;
    const float l2g[2] = { -0.04580368961f, -0.00281970977f };

    float4 hb0 = *reinterpret_cast<const float4*>(fc_b + l * 8);
    float4 hb1 = *reinterpret_cast<const float4*>(fc_b + l * 8 + 4);

    // ---- wait for GEMM partials ----
    GDC_WAIT();

    float X[8];
    {
        X[0] = hb0.x; X[1] = hb0.y; X[2] = hb0.z; X[3] = hb0.w;
        X[4] = hb1.x; X[5] = hb1.y; X[6] = hb1.z; X[7] = hb1.w;
#pragma unroll
        for (int s = 0; s < KSPLIT; s++) {
            const float* pp = g_part + (size_t)s * (BATCH * NDIM) + b * NDIM + l * 8;
            float4 p0 = *reinterpret_cast<const float4*>(pp);
            float4 p1 = *reinterpret_cast<const float4*>(pp + 4);
            X[0] += p0.x; X[1] += p0.y; X[2] += p0.z; X[3] += p0.w;
            X[4] += p1.x; X[5] += p1.y; X[6] += p1.z; X[7] += p1.w;
        }
    }
    __syncthreads();

    float Xn[8];
    {
        float mu = 0.f;
#pragma unroll
        for (int d = 0; d < 8; d++) mu += X[d];
        mu *= 0.125f;
        float var = 0.f;
#pragma unroll
        for (int d = 0; d < 8; d++) { float tt = X[d] - mu; var += tt * tt; }
        var *= 0.125f;
        float inv = rsqrtf(var + 1e-5f);
#pragma unroll
        for (int d = 0; d < 8; d++) Xn[d] = (X[d] - mu) * inv * sl1s[d] + sl1b[d];
    }

    {
        const float* wq = swq + hg * 32;
        const float* wk = swk + hg * 32;
        const float* wv = swv + hg * 64;

        float q0 = 0, q1 = 0, q2 = 0, q3 = 0, k0 = 0, k1 = 0, k2 = 0, k3 = 0;
#pragma unroll
        for (int d = 0; d < 8; d++) {
            float xv = Xn[d];
            q0 += xv * wq[d * 4 + 0]; q1 += xv * wq[d * 4 + 1];
            q2 += xv * wq[d * 4 + 2]; q3 += xv * wq[d * 4 + 3];
            k0 += xv * wk[d * 4 + 0]; k1 += xv * wk[d * 4 + 1];
            k2 += xv * wk[d * 4 + 2]; k3 += xv * wk[d * 4 + 3];
        }
        float Q0 = (q0 * c0 - q1 * s0) * e0;
        float Q1 = (q1 * c0 + q0 * s0) * e0;
        float Q2 = (q2 * c1 - q3 * s1) * e1;
        float Q3 = (q3 * c1 + q2 * s1) * e1;
        float K0 = (k0 * c0 - k1 * s0) * ie0;
        float K1 = (k1 * c0 + k0 * s0) * ie0;
        float K2 = (k2 * c1 - k3 * s1) * ie1;
        float K3 = (k3 * c1 + k2 * s1) * ie1;

        float V[8];
#pragma unroll
        for (int f = 0; f < 8; f++) {
            float a = 0.f;
#pragma unroll
            for (int d = 0; d < 8; d++) a += Xn[d] * wv[d * 8 + f];
            V[f] = a;
        }

        sK4[hg][l] = make_float4(K0, K1, K2, K3);
        sV4[hg][l][0] = make_float4(V[0], V[1], V[2], V[3]);
        sV4[hg][l][1] = make_float4(V[4], V[5], V[6], V[7]);
        sGP[hg][l] = exp2f(-fl * l2g[hg]);
        float gpn = exp2f(fl * l2g[hg]);
        __syncthreads();

        float a0 = 0, a1 = 0, a2 = 0, a3 = 0, a4 = 0, a5 = 0, a6 = 0, a7 = 0;
        const float4* kp = sK4[hg];
        const float4 (*vp)[2] = sV4[hg];
        const float* gp = sGP[hg];
        for (int m = 0; m <= l; ++m) {
            float4 kv = kp[m];
            float wgt = (Q0 * kv.x + Q1 * kv.y + Q2 * kv.z + Q3 * kv.w) * gpn * gp[m];
            float4 v0 = vp[m][0], v1 = vp[m][1];
            a0 += wgt * v0.x; a1 += wgt * v0.y; a2 += wgt * v0.z; a3 += wgt * v0.w;
            a4 += wgt * v1.x; a5 += wgt * v1.y; a6 += wgt * v1.z; a7 += wgt * v1.w;
        }
        float* yr = syc[l] + hg * 8;
        yr[0] = a0; yr[1] = a1; yr[2] = a2; yr[3] = a3;
        yr[4] = a4; yr[5] = a5; yr[6] = a6; yr[7] = a7;
    }
    __syncthreads();

    if (hg == 0) {
        float yc[16];
#pragma unroll
        for (int j = 0; j < 16; j++) yc[j] = syc[l][j];

        float gn[16];
#pragma unroll
        for (int g = 0; g < 2; g++) {
            float mu = 0.f;
#pragma unroll
            for (int jj = 0; jj < 8; jj++) mu += yc[g * 8 + jj];
            mu *= 0.125f;
            float var = 0.f;
#pragma unroll
            for (int jj = 0; jj < 8; jj++) { float tt = yc[g * 8 + jj] - mu; var += tt * tt; }
            var *= 0.125f;
            float inv = rsqrtf(var + 1e-5f);
#pragma unroll
            for (int jj = 0; jj < 8; jj++)
                gn[g * 8 + jj] = (yc[g * 8 + jj] - mu) * inv * sgnw[g * 8 + jj] + sgnb[g * 8 + jj];
        }

        float msr[8] = {0, 0, 0, 0, 0, 0, 0, 0};
#pragma unroll
        for (int j = 0; j < 16; j++) {
            float gt = 0.f;
#pragma unroll
            for (int d = 0; d < 8; d++) gt += Xn[d] * swg[d * 16 + j];
            gt = gt / (1.0f + expf(-gt));
            float val = gt * gn[j];
#pragma unroll
            for (int d = 0; d < 8; d++) msr[d] += val * swo[j * 8 + d];
        }

        float Y[8], Z[8];
#pragma unroll
        for (int d = 0; d < 8; d++) Y[d] = msr[d] + X[d];
        {
            float mu = 0.f;
#pragma unroll
            for (int d = 0; d < 8; d++) mu += Y[d];
            mu *= 0.125f;
            float var = 0.f;
#pragma unroll
            for (int d = 0; d < 8; d++) { float tt = Y[d] - mu; var += tt * tt; }
            var *= 0.125f;
            float inv = rsqrtf(var + 1e-5f);
#pragma unroll
            for (int d = 0; d < 8; d++) Z[d] = (Y[d] - mu) * inv * sl2s[d] + sl2b[d];
        }

        float f1[8];
#pragma unroll
        for (int e = 0; e < 8; e++) {
            float a = sb1[e];
#pragma unroll
            for (int d = 0; d < 8; d++) a += Z[d] * sw1[d * 8 + e];
            f1[e] = 0.5f * a * (1.0f + erff(a * 0.70710678118654752f));
        }

        float p0 = 0.f, p1 = 0.f;
#pragma unroll
        for (int d = 0; d < 8; d++) {
            float a = sb2[d];
#pragma unroll
            for (int e = 0; e < 8; e++) a += f1[e] * sw2[e * 8 + d];
            float xf = a + Y[d];
            p0 += xf * g_W12[(l * 8 + d) * 2];
            p1 += xf * g_W12[(l * 8 + d) * 2 + 1];
        }

#pragma unroll
        for (int off = 16; off > 0; off >>= 1) {
            p0 += __shfl_down_sync(0xffffffffu, p0, off);
            p1 += __shfl_down_sync(0xffffffffu, p1, off);
        }
        if ((l & 31) == 0) { sRed[l >> 5][0] = p0; sRed[l >> 5][1] = p1; }
    }
    __syncthreads();
    if (tid == 0) {
        float o0 = g_ob[0], o1 = g_ob[1];
#pragma unroll
        for (int ww = 0; ww < 8; ww++) { o0 += sRed[ww][0]; o1 += sRed[ww][1]; }
        out[b * 2 + 0] = o0;
        out[b * 2 + 1] = o1;
    }
}

// ---------------- launch (PDL: programmatic stream serialization) -----------
extern "C" void kernel_launch(void* const* d_in, const int* in_sizes, int n_in,
                              void* d_out, int out_size) {
    const float* x      = (const float*)d_in[0];
    const float* fc_w   = (const float*)d_in[1];
    const float* fc_b   = (const float*)d_in[2];
    const float* ln1_s  = (const float*)d_in[3];
    const float* ln1_b  = (const float*)d_in[4];
    const float* ln2_s  = (const float*)d_in[5];
    const float* ln2_b  = (const float*)d_in[6];
    const float* Wq     = (const float*)d_in[7];
    const float* Wk     = (const float*)d_in[8];
    const float* Wv     = (const float*)d_in[9];
    const float* Wg     = (const float*)d_in[10];
    const float* Wo     = (const float*)d_in[11];
    const float* gn_w   = (const float*)d_in[12];
    const float* gn_b   = (const float*)d_in[13];
    const float* ffn_w1 = (const float*)d_in[14];
    const float* ffn_b1 = (const float*)d_in[15];
    const float* ffn_w2 = (const float*)d_in[16];
    const float* ffn_b2 = (const float*)d_in[17];
    const float* li1_w  = (const float*)d_in[18];
    const float* li1_b  = (const float*)d_in[19];
    const float* li2_w  = (const float*)d_in[20];
    const float* li2_b  = (const float*)d_in[21];

    cudaFuncSetAttribute(k_gemm, cudaFuncAttributeMaxDynamicSharedMemorySize, SMEM_BYTES);

    // prep: normal launch (convA 384 + W12 2049 blocks)
    k_prep<<<384 + NDIM + 1, 256>>>(x, li1_w, li1_b, li2_w, li2_b);

    // gemm: PDL (launches while prep drains; waits on griddepcontrol.wait)
    {
        cudaLaunchAttribute attr[1];
        attr[0].id = cudaLaunchAttributeProgrammaticStreamSerialization;
        attr[0].val.programmaticStreamSerializationAllowed = 1;
        cudaLaunchConfig_t cfg = {};
        cfg.gridDim = dim3(NDIM / BN, KSPLIT, 1);
        cfg.blockDim = dim3(256, 1, 1);
        cfg.dynamicSmemBytes = SMEM_BYTES;
        cfg.stream = 0;
        cfg.attrs = attr;
        cfg.numAttrs = 1;
        cudaLaunchKernelEx(&cfg, k_gemm, fc_w);
    }

    // fuse: PDL
    {
        cudaLaunchAttribute attr[1];
        attr[0].id = cudaLaunchAttributeProgrammaticStreamSerialization;
        attr[0].val.programmaticStreamSerializationAllowed = 1;
        cudaLaunchConfig_t cfg = {};
        cfg.gridDim = dim3(BATCH, 1, 1);
        cfg.blockDim = dim3(512, 1, 1);
        cfg.dynamicSmemBytes = 0;
        cfg.stream = 0;
        cfg.attrs = attr;
        cfg.numAttrs = 1;
        cudaLaunchKernelEx(&cfg, k_fuse, fc_b, ln1_s, ln1_b, ln2_s, ln2_b,
                           Wq, Wk, Wv, Wg, Wo, gn_w, gn_b,
                           ffn_w1, ffn_b1, ffn_w2, ffn_b2,
                           (float*)d_out);
    }
}